// round 4
// baseline (speedup 1.0000x reference)
#include <cuda_runtime.h>
#include <cuda_bf16.h>
#include <math.h>

#define B 16
#define NTOT 17064
#define NQ   (NTOT/4)        /* 4266 — every level count divisible by 4 */
#define KSEL 1000
#define MAXOUT 100
#define SCORE_THR 0.05f
#define IOU_THR 0.6f
#define NBIN 65536
#define CANDCAP 2048

typedef unsigned long long u64;

// ---------------- scratch (static device globals; no allocations) ----------------
__device__ u64          g_key[B * NTOT];
__device__ float4       g_box[B * NTOT];
__device__ int          g_cls[B * NTOT];
__device__ unsigned int g_hist[B * NBIN];      // zero-initialized at load; re-zeroed by thresh_kernel
__device__ u64          g_thr[B];
__device__ int          g_cnt[B];
__device__ u64          g_cand[B * CANDCAP];

// ---------------- kernel 1: decode (float4, 4 anchors/thread) + histogram ----------------
__global__ __launch_bounds__(256) void decode_kernel(
    const float* __restrict__ c0, const float* __restrict__ c1,
    const float* __restrict__ c2, const float* __restrict__ c3,
    const float* __restrict__ c4,
    const float* __restrict__ r0, const float* __restrict__ r1,
    const float* __restrict__ r2, const float* __restrict__ r3,
    const float* __restrict__ r4)
{
    int q = blockIdx.x * blockDim.x + threadIdx.x;
    if (q >= B * NQ) return;
    int b  = q / NQ;
    int a4 = (q - b * NQ) * 4;          // first of 4 consecutive anchors, same level/row

    int p, hw, w, stride;
    const float *cp, *rp;
    if (a4 < 12800)      { p = a4;         hw = 12800; w = 128; stride = 8;   cp = c0; rp = r0; }
    else if (a4 < 16000) { p = a4 - 12800; hw = 3200;  w = 64;  stride = 16;  cp = c1; rp = r1; }
    else if (a4 < 16800) { p = a4 - 16000; hw = 800;   w = 32;  stride = 32;  cp = c2; rp = r2; }
    else if (a4 < 17008) { p = a4 - 16800; hw = 208;   w = 16;  stride = 64;  cp = c3; rp = r3; }
    else                 { p = a4 - 17008; hw = 56;    w = 8;   stride = 128; cp = c4; rp = r4; }

    const int h4 = hw >> 2;
    const float4* cb4 = (const float4*)(cp + (size_t)b * 80 * hw + p);
    const float4* rb4 = (const float4*)(rp + (size_t)b * 4  * hw + p);

    float m1[4], m2[4];
    int   i1[4], i2[4];
    #pragma unroll
    for (int e = 0; e < 4; e++) { m1[e] = -INFINITY; m2[e] = -INFINITY; i1[e] = 0; i2[e] = 0; }

    #pragma unroll 4
    for (int c = 0; c < 80; c++) {
        float4 v4 = __ldg(cb4 + (size_t)c * h4);
        float vv[4] = {v4.x, v4.y, v4.z, v4.w};
        #pragma unroll
        for (int e = 0; e < 4; e++) {
            float v = vv[e];
            if (v > m1[e])      { m2[e] = m1[e]; i2[e] = i1[e]; m1[e] = v; i1[e] = c; }
            else if (v > m2[e]) { m2[e] = v; i2[e] = c; }
        }
    }

    float4 q0 = __ldg(rb4), q1 = __ldg(rb4 + h4), q2 = __ldg(rb4 + 2 * h4), q3 = __ldg(rb4 + 3 * h4);
    float l0[4] = {q0.x, q0.y, q0.z, q0.w};
    float l1[4] = {q1.x, q1.y, q1.z, q1.w};
    float l2[4] = {q2.x, q2.y, q2.z, q2.w};
    float l3[4] = {q3.x, q3.y, q3.z, q3.w};

    int px0 = p % w, py = p / w;
    float ccy = (float)py * (float)stride + 0.5f * (float)stride;

    size_t o = (size_t)b * NTOT + a4;
    #pragma unroll
    for (int e = 0; e < 4; e++) {
        float score = 1.0f / (1.0f + expf(-m1[e]));
        int cls = i1[e] + 1;
        float s2 = 1.0f / (1.0f + expf(-m2[e]));
        if (s2 == score && i2[e] < i1[e]) cls = i2[e] + 1;   // argmax-over-sigmoid tie

        float ccx = (float)(px0 + e) * (float)stride + 0.5f * (float)stride;
        float4 box;
        box.x = ccx - l0[e]; box.y = ccy - l1[e];
        box.z = ccx + l2[e]; box.w = ccy + l3[e];

        g_box[o + e] = box;
        g_cls[o + e] = cls;

        unsigned u = __float_as_uint(score);
        u = (u & 0x80000000u) ? ~u : (u | 0x80000000u);
        g_key[o + e] = ((u64)u << 32) | (u64)(0xFFFFFFFFu - (unsigned)(a4 + e));
        atomicAdd(&g_hist[b * NBIN + (u >> 16)], 1u);
    }
}

// ---------------- kernel 2: per-batch threshold from histogram; zero hist + counters ----------------
__global__ __launch_bounds__(1024, 1) void thresh_kernel()
{
    const int b    = blockIdx.x;
    const int tid  = threadIdx.x;
    const int wid  = tid >> 5;
    const int lane = tid & 31;
    unsigned int* hist = g_hist + (size_t)b * NBIN;
    __shared__ unsigned warptot[32];

    // thread t owns descending chunk: bins [NBIN-(t+1)*64, NBIN-t*64)
    int base = NBIN - (tid + 1) * 64;
    unsigned sum = 0;
    #pragma unroll 8
    for (int j = 0; j < 64; j++) sum += hist[base + j];

    unsigned incl = sum;
    #pragma unroll
    for (int o = 1; o < 32; o <<= 1) {
        unsigned v = __shfl_up_sync(0xffffffffu, incl, o);
        if (lane >= o) incl += v;
    }
    if (lane == 31) warptot[wid] = incl;
    __syncthreads();
    if (wid == 0) {
        unsigned v = warptot[lane];
        unsigned wi = v;
        #pragma unroll
        for (int o = 1; o < 32; o <<= 1) {
            unsigned x = __shfl_up_sync(0xffffffffu, wi, o);
            if (lane >= o) wi += x;
        }
        warptot[lane] = wi - v;   // exclusive base
    }
    __syncthreads();
    unsigned cum_incl = warptot[wid] + incl;
    unsigned cum_excl = cum_incl - sum;
    if (cum_excl < KSEL && KSEL <= (int)cum_incl) {
        unsigned running = cum_excl;
        int d = base + 63;
        for (; d >= base; --d) {
            running += hist[d];
            if (running >= KSEL) break;
        }
        g_thr[b] = ((u64)(unsigned)d) << 48;
    }
    // zero my chunk for the next replay (only my thread touched/walked these bins)
    #pragma unroll 8
    for (int j = 0; j < 64; j++) hist[base + j] = 0u;
    if (tid == 0) g_cnt[b] = 0;
}

// ---------------- kernel 3: full-grid compaction of keys >= T into per-batch cand buffers ----------------
__global__ __launch_bounds__(256) void compact_kernel()
{
    const int b    = blockIdx.y;
    const int a    = blockIdx.x * 256 + threadIdx.x;
    const int lane = threadIdx.x & 31;
    u64 T = g_thr[b];

    u64 k = 0;
    bool take = false;
    if (a < NTOT) {
        k = g_key[(size_t)b * NTOT + a];
        take = (k >= T);
    }
    unsigned bal = __ballot_sync(0xffffffffu, take);
    if (bal) {
        int leader = __ffs(bal) - 1;
        int basepos = 0;
        if (lane == leader) basepos = atomicAdd(&g_cnt[b], __popc(bal));
        basepos = __shfl_sync(0xffffffffu, basepos, leader);
        if (take) {
            int pos = basepos + __popc(bal & ((1u << lane) - 1u));
            if (pos < CANDCAP) g_cand[(size_t)b * CANDCAP + pos] = k;
        }
    }
}

// ---------------- kernel 4: per-batch sort (hybrid 2048 bitonic) + DIoU-NMS + output ----------------
__global__ __launch_bounds__(1024, 1) void select_nms_kernel(float* __restrict__ out)
{
    const int b    = blockIdx.x;
    const int tid  = threadIdx.x;
    const int wid  = tid >> 5;
    const int lane = tid & 31;

    __shared__ u64   sm[2048];                        // 16KB: sort buffer, later x1/y1/x2/y2
    __shared__ float sar[1024], scx[1024], scy[1024]; // 12KB
    __shared__ int   skeep[1024];                     // 4KB
    __shared__ unsigned warptot[32];
    __shared__ float warpred[32];
    __shared__ float s_maxc;

    float* sx1 = (float*)&sm[0];
    float* sy1 = (float*)&sm[512];
    float* sx2 = (float*)&sm[1024];
    float* sy2 = (float*)&sm[1536];

    int C = g_cnt[b];
    if (C > CANDCAP) C = CANDCAP;
    u64 v0 = (tid        < C) ? g_cand[(size_t)b * CANDCAP + tid]        : 0ULL;
    u64 v1 = (tid + 1024 < C) ? g_cand[(size_t)b * CANDCAP + tid + 1024] : 0ULL;

    // ---- hybrid bitonic sort ascending over 2048 (2 elems/thread in registers) ----
    const int i1x = tid + 1024;
    for (int kk = 2; kk <= 2048; kk <<= 1) {
        for (int j = kk >> 1; j > 0; j >>= 1) {
            if (j >= 1024) {                     // kk==2048: partner is in-thread
                if (v0 > v1) { u64 t = v0; v0 = v1; v1 = t; }
            } else if (j >= 32) {                // cross-warp: smem exchange
                sm[tid] = v0; sm[i1x] = v1;
                __syncthreads();
                u64 p0 = sm[tid ^ j], p1 = sm[(tid ^ j) + 1024];
                __syncthreads();
                bool tm0 = (((tid & kk) == 0) == ((tid & j) == 0));
                bool tm1 = (((i1x & kk) == 0) == ((i1x & j) == 0));
                v0 = tm0 ? (v0 < p0 ? v0 : p0) : (v0 > p0 ? v0 : p0);
                v1 = tm1 ? (v1 < p1 ? v1 : p1) : (v1 > p1 ? v1 : p1);
            } else {                             // in-warp: shuffle exchange
                u64 p0 = __shfl_xor_sync(0xffffffffu, v0, j);
                u64 p1 = __shfl_xor_sync(0xffffffffu, v1, j);
                bool tm0 = (((tid & kk) == 0) == ((tid & j) == 0));
                bool tm1 = (((i1x & kk) == 0) == ((i1x & j) == 0));
                v0 = tm0 ? (v0 < p0 ? v0 : p0) : (v0 > p0 ? v0 : p0);
                v1 = tm1 ? (v1 < p1 ? v1 : p1) : (v1 > p1 ? v1 : p1);
            }
        }
    }
    sm[tid] = v0; sm[i1x] = v1;
    __syncthreads();

    // ---- gather rank-tid detection (C >= KSEL guaranteed by threshold) ----
    bool have = (tid < KSEL);
    float score = -2.0f; int mycls = 0; float4 mybox = make_float4(0, 0, 0, 0);
    if (have) {
        u64 mk = sm[2047 - tid];                 // tid-th largest
        unsigned idx = 0xFFFFFFFFu - (unsigned)(mk & 0xFFFFFFFFull);
        unsigned su  = (unsigned)(mk >> 32);
        su = (su & 0x80000000u) ? (su & 0x7FFFFFFFu) : ~su;
        score = __uint_as_float(su);
        mycls = g_cls[(size_t)b * NTOT + idx];
        mybox = g_box[(size_t)b * NTOT + idx];
    }
    bool valid = have && (score >= SCORE_THR);

    // ---- max coordinate over valid boxes ----
    float mc = valid ? fmaxf(fmaxf(mybox.x, mybox.y), fmaxf(mybox.z, mybox.w)) : -INFINITY;
    for (int o = 16; o; o >>= 1) mc = fmaxf(mc, __shfl_xor_sync(0xffffffffu, mc, o));
    if (lane == 0) warpred[wid] = mc;
    __syncthreads();
    if (tid < 32) {
        float v = warpred[tid];
        for (int o = 16; o; o >>= 1) v = fmaxf(v, __shfl_xor_sync(0xffffffffu, v, o));
        if (tid == 0) s_maxc = v;
    }
    __syncthreads();
    float maxc = s_maxc;

    // ---- class-offset shift (BEFORE area/center, like the reference) ----
    float off = (float)mycls * (maxc + 1.0f);
    float x1 = mybox.x + off, y1 = mybox.y + off;
    float x2 = mybox.z + off, y2 = mybox.w + off;
    float area = (x2 - x1 + 1.0f) * (y2 - y1 + 1.0f);
    float cx = (x1 + x2) * 0.5f, cy = (y1 + y2) * 0.5f;
    __syncthreads();   // sm reads done; alias region reusable
    sx1[tid] = x1; sy1[tid] = y1; sx2[tid] = x2; sy2[tid] = y2;
    sar[tid] = area; scx[tid] = cx; scy[tid] = cy;
    skeep[tid] = valid ? 1 : 0;
    __syncthreads();

    // ---- serial greedy DIoU-NMS with early termination at MAXOUT kept ----
    int keepj = skeep[tid];
    int kept_so_far = 0;               // identical across threads
    for (int i = 0; i < KSEL; i++) {
        int ki = skeep[i];
        if (ki && keepj && tid > i) {
            float xmin = fmaxf(sx1[i], x1);
            float ymin = fmaxf(sy1[i], y1);
            float xmax = fminf(sx2[i], x2);
            float ymax = fminf(sy2[i], y2);
            float inter = fmaxf(xmax - xmin, 0.0f) * fmaxf(ymax - ymin, 0.0f);
            float denom = sar[i] + area - inter;
            if (inter > IOU_THR * denom) {      // conservative: diou <= iou
                float iou = inter / denom;
                float dx = scx[i] - cx, dy = scy[i] - cy;
                float idg = dx * dx + dy * dy;
                float ox = fmaxf(sx2[i], x2) - fminf(sx1[i], x1);
                float oy = fmaxf(sy2[i], y2) - fminf(sy1[i], y1);
                float odg = ox * ox + oy * oy;
                float diou = iou - idg / fmaxf(odg, 1e-12f);
                if (diou > IOU_THR) { keepj = 0; skeep[tid] = 0; }
            }
        }
        kept_so_far += ki;
        __syncthreads();
        if (kept_so_far >= MAXOUT) break;   // uniform decision
    }

    // ---- rank via ballot scan ----
    unsigned bal = __ballot_sync(0xffffffffu, keepj != 0);
    int laneprefix = __popc(bal & ((1u << lane) - 1u));
    if (lane == 0) warptot[wid] = __popc(bal);
    __syncthreads();
    if (wid == 0) {
        unsigned v = warptot[lane];
        unsigned wi = v;
        #pragma unroll
        for (int o = 1; o < 32; o <<= 1) {
            unsigned x = __shfl_up_sync(0xffffffffu, wi, o);
            if (lane >= o) wi += x;
        }
        warptot[lane] = wi - v;
    }
    __syncthreads();
    int rank = (int)warptot[wid] + laneprefix;

    // ---- output: scores [B,100] || classes [B,100] || boxes [B,100,4], all f32 ----
    float* oS = out + (size_t)b * MAXOUT;
    float* oC = out + (size_t)B * MAXOUT + (size_t)b * MAXOUT;
    float* oB = out + (size_t)2 * B * MAXOUT + (size_t)b * MAXOUT * 4;
    if (tid < MAXOUT) {
        oS[tid] = -2.0f; oC[tid] = -2.0f;
        oB[tid * 4 + 0] = -2.0f; oB[tid * 4 + 1] = -2.0f;
        oB[tid * 4 + 2] = -2.0f; oB[tid * 4 + 3] = -2.0f;
    }
    __syncthreads();
    if (keepj && rank < MAXOUT) {
        oS[rank] = score;
        oC[rank] = (float)mycls;
        oB[rank * 4 + 0] = mybox.x; oB[rank * 4 + 1] = mybox.y;
        oB[rank * 4 + 2] = mybox.z; oB[rank * 4 + 3] = mybox.w;
    }
}

// ---------------- launch ----------------
extern "C" void kernel_launch(void* const* d_in, const int* in_sizes, int n_in,
                              void* d_out, int out_size)
{
    const float* cls[5] = {0,0,0,0,0};
    const float* reg[5] = {0,0,0,0,0};
    for (int i = 0; i < n_in; i++) {
        switch (in_sizes[i]) {
            case 16384000: cls[0] = (const float*)d_in[i]; break;
            case  4096000: cls[1] = (const float*)d_in[i]; break;
            case  1024000: cls[2] = (const float*)d_in[i]; break;
            case   266240: cls[3] = (const float*)d_in[i]; break;
            case    71680: cls[4] = (const float*)d_in[i]; break;
            case   819200: reg[0] = (const float*)d_in[i]; break;
            case   204800: reg[1] = (const float*)d_in[i]; break;
            case    51200: reg[2] = (const float*)d_in[i]; break;
            case    13312: reg[3] = (const float*)d_in[i]; break;
            case     3584: reg[4] = (const float*)d_in[i]; break;
            default: break; // anchors (unused)
        }
    }
    decode_kernel<<<(B * NQ + 255) / 256, 256>>>(
        cls[0], cls[1], cls[2], cls[3], cls[4],
        reg[0], reg[1], reg[2], reg[3], reg[4]);
    thresh_kernel<<<B, 1024>>>();
    compact_kernel<<<dim3((NTOT + 255) / 256, B), 256>>>();
    select_nms_kernel<<<B, 1024>>>((float*)d_out);
}

// round 5
// speedup vs baseline: 1.7475x; 1.7475x over previous
#include <cuda_runtime.h>
#include <cuda_bf16.h>
#include <math.h>

#define B 16
#define NTOT 17064
#define NPAD 17408          // NTOT padded to multiple of 1024 (uniform warp trips)
#define KSEL 1000
#define MAXOUT 100
#define SCORE_THR 0.05f
#define IOU_THR 0.6f
#define CANDCAP 2048
#define FASTN 256

typedef unsigned long long u64;

// ---------------- scratch (static device globals; no allocations) ----------------
__device__ u64    g_key[B * NTOT];
__device__ float4 g_box[B * NTOT];
__device__ int    g_cls[B * NTOT];

// ---------------- kernel 1: decode (scalar, proven fast) ----------------
__global__ __launch_bounds__(256) void decode_kernel(
    const float* __restrict__ c0, const float* __restrict__ c1,
    const float* __restrict__ c2, const float* __restrict__ c3,
    const float* __restrict__ c4,
    const float* __restrict__ r0, const float* __restrict__ r1,
    const float* __restrict__ r2, const float* __restrict__ r3,
    const float* __restrict__ r4)
{
    int t = blockIdx.x * blockDim.x + threadIdx.x;
    if (t >= B * NTOT) return;
    int b = t / NTOT;
    int a = t - b * NTOT;

    int p, hw, w, stride;
    const float *cp, *rp;
    if (a < 12800)      { p = a;         hw = 12800; w = 128; stride = 8;   cp = c0; rp = r0; }
    else if (a < 16000) { p = a - 12800; hw = 3200;  w = 64;  stride = 16;  cp = c1; rp = r1; }
    else if (a < 16800) { p = a - 16000; hw = 800;   w = 32;  stride = 32;  cp = c2; rp = r2; }
    else if (a < 17008) { p = a - 16800; hw = 208;   w = 16;  stride = 64;  cp = c3; rp = r3; }
    else                { p = a - 17008; hw = 56;    w = 8;   stride = 128; cp = c4; rp = r4; }

    // max + argmax over 80 class logits (track top-2 for sigmoid-tie semantics)
    const float* cb = cp + ((size_t)b * 80) * hw + p;
    float m1 = -INFINITY, m2 = -INFINITY;
    int i1 = 0, i2 = 0;
    #pragma unroll 8
    for (int c = 0; c < 80; c++) {
        float v = __ldg(cb + (size_t)c * hw);
        if (v > m1) { m2 = m1; i2 = i1; m1 = v; i1 = c; }
        else if (v > m2) { m2 = v; i2 = c; }
    }
    float score = 1.0f / (1.0f + expf(-m1));
    int cls = i1 + 1;
    {   // replicate jnp.argmax-over-sigmoid first-occurrence ties
        float s2 = 1.0f / (1.0f + expf(-m2));
        if (s2 == score && i2 < i1) cls = i2 + 1;
    }

    // decode box
    float px = (float)(p % w), py = (float)(p / w);
    float ccx = px * (float)stride + 0.5f * (float)stride;
    float ccy = py * (float)stride + 0.5f * (float)stride;
    const float* rb = rp + ((size_t)b * 4) * hw + p;
    float rr0 = rb[0];
    float rr1 = rb[(size_t)hw];
    float rr2 = rb[(size_t)2 * hw];
    float rr3 = rb[(size_t)3 * hw];
    float4 box;
    box.x = ccx - rr0; box.y = ccy - rr1;
    box.z = ccx + rr2; box.w = ccy + rr3;

    size_t o = (size_t)b * NTOT + a;
    g_box[o] = box;
    g_cls[o] = cls;

    // key: descending score, ties -> lower index first (matches lax.top_k)
    unsigned u = __float_as_uint(score);
    u = (u & 0x80000000u) ? ~u : (u | 0x80000000u);
    g_key[o] = ((u64)u << 32) | (u64)(0xFFFFFFFFu - (unsigned)a);
}

// warp-aggregated histogram add (all 32 lanes must reach this call)
__device__ __forceinline__ void agg_hist(unsigned int* hist, unsigned d, bool match)
{
    unsigned active = __ballot_sync(0xffffffffu, match);
    if (match) {
        unsigned peers = __match_any_sync(active, d);
        int leader = __ffs(peers) - 1;
        if ((int)(threadIdx.x & 31) == leader)
            atomicAdd(&hist[d], (unsigned)__popc(peers));
    }
}

// ---------------- kernel 2: per-batch select (2x10-bit radix) + sort + NMS + output ----------------
__global__ __launch_bounds__(1024, 1) void select_nms_kernel(float* __restrict__ out)
{
    const int b    = blockIdx.x;
    const int tid  = threadIdx.x;
    const int wid  = tid >> 5;
    const int lane = tid & 31;
    const u64* keys = g_key + (size_t)b * NTOT;

    __shared__ u64      sm[2048];                        // 16KB: cand/sort, later x1/y1/x2/y2
    __shared__ float    sar[1024], scx[1024], scy[1024]; // 12KB
    __shared__ int      skeep[1024];                     // 4KB
    __shared__ unsigned hist[1024];                      // 4KB
    __shared__ unsigned warptot[32];
    __shared__ float    warpred[32];
    __shared__ float    s_maxc;
    __shared__ int      s_cnt, s_d1, s_d2, s_K, s_fastkept;

    float* sx1 = (float*)&sm[0];
    float* sy1 = (float*)&sm[512];
    float* sx2 = (float*)&sm[1024];
    float* sy2 = (float*)&sm[1536];

    hist[tid] = 0u;
    if (tid == 0) { s_cnt = 0; s_d1 = 0; s_d2 = 0; s_K = KSEL; s_fastkept = 0; }
    __syncthreads();

    // ---- pass 1: 10-bit hist of u>>22 ----
    for (int i = tid; i < NPAD; i += 1024) {
        unsigned u = (i < NTOT) ? (unsigned)(keys[i] >> 32) : 0u;
        agg_hist(hist, u >> 22, i < NTOT);
    }
    __syncthreads();
    // suffix scan (descending bins): thread t owns bin 1023-t
    {
        int bin = 1023 - tid;
        unsigned sum = hist[bin];
        unsigned incl = sum;
        #pragma unroll
        for (int o = 1; o < 32; o <<= 1) {
            unsigned v = __shfl_up_sync(0xffffffffu, incl, o);
            if (lane >= o) incl += v;
        }
        if (lane == 31) warptot[wid] = incl;
        __syncthreads();
        if (wid == 0) {
            unsigned v = warptot[lane];
            unsigned wi = v;
            #pragma unroll
            for (int o = 1; o < 32; o <<= 1) {
                unsigned x = __shfl_up_sync(0xffffffffu, wi, o);
                if (lane >= o) wi += x;
            }
            warptot[lane] = wi - v;
        }
        __syncthreads();
        unsigned cum_incl = warptot[wid] + incl;
        unsigned cum_excl = cum_incl - sum;
        if (cum_excl < (unsigned)KSEL && (unsigned)KSEL <= cum_incl) {
            s_d1 = bin; s_K = KSEL - (int)cum_excl;
        }
        __syncthreads();
    }
    const unsigned d1 = (unsigned)s_d1;
    const int K2 = s_K;
    hist[tid] = 0u;
    __syncthreads();

    // ---- pass 2: refine within bin d1 on (u>>12)&1023 ----
    for (int i = tid; i < NPAD; i += 1024) {
        unsigned u = (i < NTOT) ? (unsigned)(keys[i] >> 32) : 0u;
        bool match = (i < NTOT) && ((u >> 22) == d1);
        agg_hist(hist, (u >> 12) & 1023u, match);
    }
    __syncthreads();
    {
        int bin = 1023 - tid;
        unsigned sum = hist[bin];
        unsigned incl = sum;
        #pragma unroll
        for (int o = 1; o < 32; o <<= 1) {
            unsigned v = __shfl_up_sync(0xffffffffu, incl, o);
            if (lane >= o) incl += v;
        }
        if (lane == 31) warptot[wid] = incl;
        __syncthreads();
        if (wid == 0) {
            unsigned v = warptot[lane];
            unsigned wi = v;
            #pragma unroll
            for (int o = 1; o < 32; o <<= 1) {
                unsigned x = __shfl_up_sync(0xffffffffu, wi, o);
                if (lane >= o) wi += x;
            }
            warptot[lane] = wi - v;
        }
        __syncthreads();
        unsigned cum_incl = warptot[wid] + incl;
        unsigned cum_excl = cum_incl - sum;
        if (cum_excl < (unsigned)K2 && (unsigned)K2 <= cum_incl) s_d2 = bin;
        __syncthreads();
    }
    const u64 T = ((u64)((d1 << 10) | (unsigned)s_d2)) << 44;   // exact 20-bit threshold

    // ---- compact keys >= T into sm (warp-aggregated slot allocation) ----
    for (int i = tid; i < NPAD; i += 1024) {
        u64 k = (i < NTOT) ? keys[i] : 0ULL;
        bool take = (i < NTOT) && (k >= T);
        unsigned bal = __ballot_sync(0xffffffffu, take);
        if (bal) {
            int leader = __ffs(bal) - 1;
            int basepos = 0;
            if (lane == leader) basepos = atomicAdd(&s_cnt, __popc(bal));
            basepos = __shfl_sync(0xffffffffu, basepos, leader);
            if (take) {
                int pos = basepos + __popc(bal & ((1u << lane) - 1u));
                if (pos < CANDCAP) sm[pos] = k;
            }
        }
    }
    __syncthreads();
    int C = s_cnt; if (C > CANDCAP) C = CANDCAP;
    for (int i = C + tid; i < CANDCAP; i += 1024) sm[i] = 0ULL;
    __syncthreads();

    u64 v0 = sm[tid], v1 = sm[tid + 1024];
    __syncthreads();

    // ---- hybrid bitonic sort ascending over 2048 (2 elems/thread in registers) ----
    const int i1x = tid + 1024;
    for (int kk = 2; kk <= 2048; kk <<= 1) {
        for (int j = kk >> 1; j > 0; j >>= 1) {
            if (j >= 1024) {                     // kk==2048: partner is in-thread
                if (v0 > v1) { u64 t = v0; v0 = v1; v1 = t; }
            } else if (j >= 32) {                // cross-warp: smem exchange
                sm[tid] = v0; sm[i1x] = v1;
                __syncthreads();
                u64 p0 = sm[tid ^ j], p1 = sm[(tid ^ j) + 1024];
                __syncthreads();
                bool tm0 = (((tid & kk) == 0) == ((tid & j) == 0));
                bool tm1 = (((i1x & kk) == 0) == ((i1x & j) == 0));
                v0 = tm0 ? (v0 < p0 ? v0 : p0) : (v0 > p0 ? v0 : p0);
                v1 = tm1 ? (v1 < p1 ? v1 : p1) : (v1 > p1 ? v1 : p1);
            } else {                             // in-warp: shuffle exchange
                u64 p0 = __shfl_xor_sync(0xffffffffu, v0, j);
                u64 p1 = __shfl_xor_sync(0xffffffffu, v1, j);
                bool tm0 = (((tid & kk) == 0) == ((tid & j) == 0));
                bool tm1 = (((i1x & kk) == 0) == ((i1x & j) == 0));
                v0 = tm0 ? (v0 < p0 ? v0 : p0) : (v0 > p0 ? v0 : p0);
                v1 = tm1 ? (v1 < p1 ? v1 : p1) : (v1 > p1 ? v1 : p1);
            }
        }
    }
    sm[tid] = v0; sm[i1x] = v1;
    __syncthreads();

    // ---- gather rank-tid detection ----
    bool have = (tid < KSEL);
    float score = -2.0f; int mycls = 0; float4 mybox = make_float4(0, 0, 0, 0);
    if (have) {
        u64 mk = sm[2047 - tid];                 // tid-th largest
        unsigned idx = 0xFFFFFFFFu - (unsigned)(mk & 0xFFFFFFFFull);
        unsigned su  = (unsigned)(mk >> 32);
        su = (su & 0x80000000u) ? (su & 0x7FFFFFFFu) : ~su;
        score = __uint_as_float(su);
        mycls = g_cls[(size_t)b * NTOT + idx];
        mybox = g_box[(size_t)b * NTOT + idx];
    }
    bool valid = have && (score >= SCORE_THR);

    // ---- max coordinate over valid boxes ----
    float mc = valid ? fmaxf(fmaxf(mybox.x, mybox.y), fmaxf(mybox.z, mybox.w)) : -INFINITY;
    for (int o = 16; o; o >>= 1) mc = fmaxf(mc, __shfl_xor_sync(0xffffffffu, mc, o));
    if (lane == 0) warpred[wid] = mc;
    __syncthreads();
    if (tid < 32) {
        float v = warpred[tid];
        for (int o = 16; o; o >>= 1) v = fmaxf(v, __shfl_xor_sync(0xffffffffu, v, o));
        if (tid == 0) s_maxc = v;
    }
    __syncthreads();
    float maxc = s_maxc;

    // ---- class-offset shift (BEFORE area/center, like the reference) ----
    float off = (float)mycls * (maxc + 1.0f);
    float x1 = mybox.x + off, y1 = mybox.y + off;
    float x2 = mybox.z + off, y2 = mybox.w + off;
    float area = (x2 - x1 + 1.0f) * (y2 - y1 + 1.0f);
    float cx = (x1 + x2) * 0.5f, cy = (y1 + y2) * 0.5f;
    __syncthreads();   // sm reads done; alias region reusable
    sx1[tid] = x1; sy1[tid] = y1; sx2[tid] = x2; sy2[tid] = y2;
    sar[tid] = area; scx[tid] = cx; scy[tid] = cy;
    skeep[tid] = valid ? 1 : 0;
    __syncthreads();

    // ---- fast-path NMS: first FASTN rows, 8 warps, named barrier ----
    // Rows < FASTN are fully resolved by suppressors < FASTN. If >=MAXOUT kept
    // among them, all later rows have rank >= MAXOUT -> discarded (exact).
    if (tid < FASTN) {
        int keepf = skeep[tid];
        int kept = 0;
        for (int i = 0; i < FASTN; i++) {
            int ki = skeep[i];
            if (ki && keepf && tid > i) {
                float xmin = fmaxf(sx1[i], x1);
                float ymin = fmaxf(sy1[i], y1);
                float xmax = fminf(sx2[i], x2);
                float ymax = fminf(sy2[i], y2);
                float inter = fmaxf(xmax - xmin, 0.0f) * fmaxf(ymax - ymin, 0.0f);
                float denom = sar[i] + area - inter;
                if (inter > IOU_THR * denom) {      // conservative: diou <= iou
                    float iou = inter / denom;
                    float dx = scx[i] - cx, dy = scy[i] - cy;
                    float idg = dx * dx + dy * dy;
                    float ox = fmaxf(sx2[i], x2) - fminf(sx1[i], x1);
                    float oy = fmaxf(sy2[i], y2) - fminf(sy1[i], y1);
                    float odg = ox * ox + oy * oy;
                    float diou = iou - idg / fmaxf(odg, 1e-12f);
                    if (diou > IOU_THR) { keepf = 0; skeep[tid] = 0; }
                }
            }
            kept += ki;
            asm volatile("bar.sync 1, 256;" ::: "memory");
            if (kept >= MAXOUT) break;              // uniform among 256
        }
        if (tid == 0) s_fastkept = kept;
    }
    __syncthreads();

    int keepj;
    if (s_fastkept >= MAXOUT) {
        keepj = skeep[tid];          // rows >= FASTN: rank >= MAXOUT, dropped below
    } else {
        // ---- fallback: exact full 1000-row loop (reset + rerun) ----
        skeep[tid] = valid ? 1 : 0;
        __syncthreads();
        keepj = skeep[tid];
        int kept_so_far = 0;
        for (int i = 0; i < KSEL; i++) {
            int ki = skeep[i];
            if (ki && keepj && tid > i) {
                float xmin = fmaxf(sx1[i], x1);
                float ymin = fmaxf(sy1[i], y1);
                float xmax = fminf(sx2[i], x2);
                float ymax = fminf(sy2[i], y2);
                float inter = fmaxf(xmax - xmin, 0.0f) * fmaxf(ymax - ymin, 0.0f);
                float denom = sar[i] + area - inter;
                if (inter > IOU_THR * denom) {
                    float iou = inter / denom;
                    float dx = scx[i] - cx, dy = scy[i] - cy;
                    float idg = dx * dx + dy * dy;
                    float ox = fmaxf(sx2[i], x2) - fminf(sx1[i], x1);
                    float oy = fmaxf(sy2[i], y2) - fminf(sy1[i], y1);
                    float odg = ox * ox + oy * oy;
                    float diou = iou - idg / fmaxf(odg, 1e-12f);
                    if (diou > IOU_THR) { keepj = 0; skeep[tid] = 0; }
                }
            }
            kept_so_far += ki;
            __syncthreads();
            if (kept_so_far >= MAXOUT) break;       // uniform
        }
    }

    // ---- rank via ballot scan ----
    unsigned bal = __ballot_sync(0xffffffffu, keepj != 0);
    int laneprefix = __popc(bal & ((1u << lane) - 1u));
    if (lane == 0) warptot[wid] = __popc(bal);
    __syncthreads();
    if (wid == 0) {
        unsigned v = warptot[lane];
        unsigned wi = v;
        #pragma unroll
        for (int o = 1; o < 32; o <<= 1) {
            unsigned x = __shfl_up_sync(0xffffffffu, wi, o);
            if (lane >= o) wi += x;
        }
        warptot[lane] = wi - v;
    }
    __syncthreads();
    int rank = (int)warptot[wid] + laneprefix;

    // ---- output: scores [B,100] || classes [B,100] || boxes [B,100,4], all f32 ----
    float* oS = out + (size_t)b * MAXOUT;
    float* oC = out + (size_t)B * MAXOUT + (size_t)b * MAXOUT;
    float* oB = out + (size_t)2 * B * MAXOUT + (size_t)b * MAXOUT * 4;
    if (tid < MAXOUT) {
        oS[tid] = -2.0f; oC[tid] = -2.0f;
        oB[tid * 4 + 0] = -2.0f; oB[tid * 4 + 1] = -2.0f;
        oB[tid * 4 + 2] = -2.0f; oB[tid * 4 + 3] = -2.0f;
    }
    __syncthreads();
    if (keepj && rank < MAXOUT) {
        oS[rank] = score;
        oC[rank] = (float)mycls;
        oB[rank * 4 + 0] = mybox.x; oB[rank * 4 + 1] = mybox.y;
        oB[rank * 4 + 2] = mybox.z; oB[rank * 4 + 3] = mybox.w;
    }
}

// ---------------- launch ----------------
extern "C" void kernel_launch(void* const* d_in, const int* in_sizes, int n_in,
                              void* d_out, int out_size)
{
    const float* cls[5] = {0,0,0,0,0};
    const float* reg[5] = {0,0,0,0,0};
    for (int i = 0; i < n_in; i++) {
        switch (in_sizes[i]) {
            case 16384000: cls[0] = (const float*)d_in[i]; break;
            case  4096000: cls[1] = (const float*)d_in[i]; break;
            case  1024000: cls[2] = (const float*)d_in[i]; break;
            case   266240: cls[3] = (const float*)d_in[i]; break;
            case    71680: cls[4] = (const float*)d_in[i]; break;
            case   819200: reg[0] = (const float*)d_in[i]; break;
            case   204800: reg[1] = (const float*)d_in[i]; break;
            case    51200: reg[2] = (const float*)d_in[i]; break;
            case    13312: reg[3] = (const float*)d_in[i]; break;
            case     3584: reg[4] = (const float*)d_in[i]; break;
            default: break; // anchors (unused)
        }
    }
    int total = B * NTOT;
    decode_kernel<<<(total + 255) / 256, 256>>>(
        cls[0], cls[1], cls[2], cls[3], cls[4],
        reg[0], reg[1], reg[2], reg[3], reg[4]);
    select_nms_kernel<<<B, 1024>>>((float*)d_out);
}

// round 6
// speedup vs baseline: 1.7830x; 1.0203x over previous
#include <cuda_runtime.h>
#include <cuda_bf16.h>
#include <math.h>

#define B 16
#define NTOT 17064
#define KSEL 1000
#define MAXOUT 100
#define SCORE_THR 0.05f
#define IOU_THR 0.6f
#define CANDCAP 2048
#define FASTN 128

typedef unsigned long long u64;

// ---------------- scratch (static device globals; no allocations) ----------------
__device__ u64      g_key[B * NTOT];
__device__ float4   g_box[B * NTOT];
__device__ int      g_cls[B * NTOT];
__device__ unsigned g_hist1[B * 1024];   // zero-init; re-zeroed by thresh1
__device__ unsigned g_hist2[B * 1024];   // zero-init; re-zeroed by thresh2
__device__ int      g_d1[B];
__device__ int      g_K2[B];
__device__ unsigned g_thrU[B];
__device__ int      g_cnt[B];
__device__ u64      g_cand[B * CANDCAP];

// ---------------- kernel 1: decode + 10-bit coarse histogram ----------------
__global__ __launch_bounds__(256) void decode_kernel(
    const float* __restrict__ c0, const float* __restrict__ c1,
    const float* __restrict__ c2, const float* __restrict__ c3,
    const float* __restrict__ c4,
    const float* __restrict__ r0, const float* __restrict__ r1,
    const float* __restrict__ r2, const float* __restrict__ r3,
    const float* __restrict__ r4)
{
    int t = blockIdx.x * blockDim.x + threadIdx.x;
    if (t >= B * NTOT) return;
    int b = t / NTOT;
    int a = t - b * NTOT;

    int p, hw, w, stride;
    const float *cp, *rp;
    if (a < 12800)      { p = a;         hw = 12800; w = 128; stride = 8;   cp = c0; rp = r0; }
    else if (a < 16000) { p = a - 12800; hw = 3200;  w = 64;  stride = 16;  cp = c1; rp = r1; }
    else if (a < 16800) { p = a - 16000; hw = 800;   w = 32;  stride = 32;  cp = c2; rp = r2; }
    else if (a < 17008) { p = a - 16800; hw = 208;   w = 16;  stride = 64;  cp = c3; rp = r3; }
    else                { p = a - 17008; hw = 56;    w = 8;   stride = 128; cp = c4; rp = r4; }

    // max + argmax over 80 class logits (track top-2 for sigmoid-tie semantics)
    const float* cb = cp + ((size_t)b * 80) * hw + p;
    float m1 = -INFINITY, m2 = -INFINITY;
    int i1 = 0, i2 = 0;
    #pragma unroll 8
    for (int c = 0; c < 80; c++) {
        float v = __ldg(cb + (size_t)c * hw);
        if (v > m1) { m2 = m1; i2 = i1; m1 = v; i1 = c; }
        else if (v > m2) { m2 = v; i2 = c; }
    }
    float score = 1.0f / (1.0f + expf(-m1));
    int cls = i1 + 1;
    {   // replicate jnp.argmax-over-sigmoid first-occurrence ties
        float s2 = 1.0f / (1.0f + expf(-m2));
        if (s2 == score && i2 < i1) cls = i2 + 1;
    }

    // decode box
    float px = (float)(p % w), py = (float)(p / w);
    float ccx = px * (float)stride + 0.5f * (float)stride;
    float ccy = py * (float)stride + 0.5f * (float)stride;
    const float* rb = rp + ((size_t)b * 4) * hw + p;
    float rr0 = rb[0];
    float rr1 = rb[(size_t)hw];
    float rr2 = rb[(size_t)2 * hw];
    float rr3 = rb[(size_t)3 * hw];
    float4 box;
    box.x = ccx - rr0; box.y = ccy - rr1;
    box.z = ccx + rr2; box.w = ccy + rr3;

    size_t o = (size_t)b * NTOT + a;
    g_box[o] = box;
    g_cls[o] = cls;

    // key: descending score, ties -> lower index first (matches lax.top_k)
    unsigned u = __float_as_uint(score);
    u = (u & 0x80000000u) ? ~u : (u | 0x80000000u);
    g_key[o] = ((u64)u << 32) | (u64)(0xFFFFFFFFu - (unsigned)a);

    // warp-aggregated coarse histogram add (aggregate on (b,bin))
    unsigned bin = u >> 22;
    unsigned mask = __activemask();
    unsigned peers = __match_any_sync(mask, (unsigned)(b << 10) | bin);
    int leader = __ffs(peers) - 1;
    if ((int)(threadIdx.x & 31) == leader)
        atomicAdd(&g_hist1[b * 1024 + bin], (unsigned)__popc(peers));
}

// block suffix-scan helper state is inline below (per-kernel)

// ---------------- kernel 2: coarse threshold bin per batch ----------------
__global__ __launch_bounds__(1024, 1) void thresh1_kernel()
{
    const int b    = blockIdx.x;
    const int tid  = threadIdx.x;
    const int wid  = tid >> 5;
    const int lane = tid & 31;
    __shared__ unsigned warptot[32];

    int bin = 1023 - tid;                       // descending ownership
    unsigned sum = g_hist1[b * 1024 + bin];
    unsigned incl = sum;
    #pragma unroll
    for (int o = 1; o < 32; o <<= 1) {
        unsigned v = __shfl_up_sync(0xffffffffu, incl, o);
        if (lane >= o) incl += v;
    }
    if (lane == 31) warptot[wid] = incl;
    __syncthreads();
    if (wid == 0) {
        unsigned v = warptot[lane];
        unsigned wi = v;
        #pragma unroll
        for (int o = 1; o < 32; o <<= 1) {
            unsigned x = __shfl_up_sync(0xffffffffu, wi, o);
            if (lane >= o) wi += x;
        }
        warptot[lane] = wi - v;                 // exclusive base
    }
    __syncthreads();
    unsigned cum_incl = warptot[wid] + incl;
    unsigned cum_excl = cum_incl - sum;
    if (cum_excl < (unsigned)KSEL && (unsigned)KSEL <= cum_incl) {
        g_d1[b] = bin;
        g_K2[b] = KSEL - (int)cum_excl;
    }
    g_hist1[b * 1024 + bin] = 0u;               // re-zero for next replay
    if (tid == 0) g_cnt[b] = 0;
}

// ---------------- kernel 3: refine histogram (full grid) ----------------
__global__ __launch_bounds__(256) void refine_kernel()
{
    const int b = blockIdx.y;
    const int a = blockIdx.x * 256 + threadIdx.x;
    if (a >= NTOT) return;
    unsigned d1 = (unsigned)g_d1[b];
    unsigned u = (unsigned)(g_key[(size_t)b * NTOT + a] >> 32);
    if ((u >> 22) == d1)
        atomicAdd(&g_hist2[b * 1024 + ((u >> 12) & 1023u)], 1u);
}

// ---------------- kernel 4: fine threshold per batch ----------------
__global__ __launch_bounds__(1024, 1) void thresh2_kernel()
{
    const int b    = blockIdx.x;
    const int tid  = threadIdx.x;
    const int wid  = tid >> 5;
    const int lane = tid & 31;
    __shared__ unsigned warptot[32];

    int K2 = g_K2[b];
    int bin = 1023 - tid;
    unsigned sum = g_hist2[b * 1024 + bin];
    unsigned incl = sum;
    #pragma unroll
    for (int o = 1; o < 32; o <<= 1) {
        unsigned v = __shfl_up_sync(0xffffffffu, incl, o);
        if (lane >= o) incl += v;
    }
    if (lane == 31) warptot[wid] = incl;
    __syncthreads();
    if (wid == 0) {
        unsigned v = warptot[lane];
        unsigned wi = v;
        #pragma unroll
        for (int o = 1; o < 32; o <<= 1) {
            unsigned x = __shfl_up_sync(0xffffffffu, wi, o);
            if (lane >= o) wi += x;
        }
        warptot[lane] = wi - v;
    }
    __syncthreads();
    unsigned cum_incl = warptot[wid] + incl;
    unsigned cum_excl = cum_incl - sum;
    if (cum_excl < (unsigned)K2 && (unsigned)K2 <= cum_incl)
        g_thrU[b] = ((unsigned)g_d1[b] << 22) | ((unsigned)bin << 12);
    g_hist2[b * 1024 + bin] = 0u;               // re-zero for next replay
}

// ---------------- kernel 5: compact (full grid, warp-aggregated) ----------------
__global__ __launch_bounds__(256) void compact_kernel()
{
    const int b    = blockIdx.y;
    const int a    = blockIdx.x * 256 + threadIdx.x;
    const int lane = threadIdx.x & 31;
    unsigned Tu = g_thrU[b];

    u64 k = 0; bool take = false;
    if (a < NTOT) {
        k = g_key[(size_t)b * NTOT + a];
        take = ((unsigned)(k >> 32) >= Tu);
    }
    unsigned bal = __ballot_sync(0xffffffffu, take);
    if (bal) {
        int leader = __ffs(bal) - 1;
        int basepos = 0;
        if (lane == leader) basepos = atomicAdd(&g_cnt[b], __popc(bal));
        basepos = __shfl_sync(0xffffffffu, basepos, leader);
        if (take) {
            int pos = basepos + __popc(bal & ((1u << lane) - 1u));
            if (pos < CANDCAP) g_cand[(size_t)b * CANDCAP + pos] = k;
        }
    }
}

// ---------------- kernel 6: per-batch sort + DIoU-NMS + output ----------------
__global__ __launch_bounds__(1024, 1) void select_nms_kernel(float* __restrict__ out)
{
    const int b    = blockIdx.x;
    const int tid  = threadIdx.x;
    const int wid  = tid >> 5;
    const int lane = tid & 31;

    __shared__ u64   sm[2048];                        // 16KB: sort buf, later x1/y1/x2/y2
    __shared__ float sar[1024], scx[1024], scy[1024]; // 12KB
    __shared__ int   skeep[1024];                     // 4KB
    __shared__ unsigned warptot[32];
    __shared__ float warpred[32];
    __shared__ float s_maxc;
    __shared__ int   s_fastkept;

    float* sx1 = (float*)&sm[0];
    float* sy1 = (float*)&sm[512];
    float* sx2 = (float*)&sm[1024];
    float* sy2 = (float*)&sm[1536];

    if (tid == 0) s_fastkept = 0;

    int C = g_cnt[b]; if (C > CANDCAP) C = CANDCAP;
    u64 v0 = (tid        < C) ? g_cand[(size_t)b * CANDCAP + tid]        : 0ULL;
    u64 v1 = (tid + 1024 < C) ? g_cand[(size_t)b * CANDCAP + tid + 1024] : 0ULL;

    // ---- hybrid bitonic sort ascending over 2048 (2 elems/thread in registers) ----
    const int i1x = tid + 1024;
    for (int kk = 2; kk <= 2048; kk <<= 1) {
        for (int j = kk >> 1; j > 0; j >>= 1) {
            if (j >= 1024) {                     // kk==2048: partner in-thread
                if (v0 > v1) { u64 t = v0; v0 = v1; v1 = t; }
            } else if (j >= 32) {                // cross-warp: smem exchange
                sm[tid] = v0; sm[i1x] = v1;
                __syncthreads();
                u64 p0 = sm[tid ^ j], p1 = sm[(tid ^ j) + 1024];
                __syncthreads();
                bool tm0 = (((tid & kk) == 0) == ((tid & j) == 0));
                bool tm1 = (((i1x & kk) == 0) == ((i1x & j) == 0));
                v0 = tm0 ? (v0 < p0 ? v0 : p0) : (v0 > p0 ? v0 : p0);
                v1 = tm1 ? (v1 < p1 ? v1 : p1) : (v1 > p1 ? v1 : p1);
            } else {                             // in-warp: shuffle exchange
                u64 p0 = __shfl_xor_sync(0xffffffffu, v0, j);
                u64 p1 = __shfl_xor_sync(0xffffffffu, v1, j);
                bool tm0 = (((tid & kk) == 0) == ((tid & j) == 0));
                bool tm1 = (((i1x & kk) == 0) == ((i1x & j) == 0));
                v0 = tm0 ? (v0 < p0 ? v0 : p0) : (v0 > p0 ? v0 : p0);
                v1 = tm1 ? (v1 < p1 ? v1 : p1) : (v1 > p1 ? v1 : p1);
            }
        }
    }
    sm[tid] = v0; sm[i1x] = v1;
    __syncthreads();

    // ---- gather rank-tid detection ----
    bool have = (tid < KSEL);
    float score = -2.0f; int mycls = 0; float4 mybox = make_float4(0, 0, 0, 0);
    if (have) {
        u64 mk = sm[2047 - tid];                 // tid-th largest
        unsigned idx = 0xFFFFFFFFu - (unsigned)(mk & 0xFFFFFFFFull);
        unsigned su  = (unsigned)(mk >> 32);
        su = (su & 0x80000000u) ? (su & 0x7FFFFFFFu) : ~su;
        score = __uint_as_float(su);
        mycls = g_cls[(size_t)b * NTOT + idx];
        mybox = g_box[(size_t)b * NTOT + idx];
    }
    bool valid = have && (score >= SCORE_THR);

    // ---- max coordinate over valid boxes ----
    float mc = valid ? fmaxf(fmaxf(mybox.x, mybox.y), fmaxf(mybox.z, mybox.w)) : -INFINITY;
    for (int o = 16; o; o >>= 1) mc = fmaxf(mc, __shfl_xor_sync(0xffffffffu, mc, o));
    if (lane == 0) warpred[wid] = mc;
    __syncthreads();
    if (tid < 32) {
        float v = warpred[tid];
        for (int o = 16; o; o >>= 1) v = fmaxf(v, __shfl_xor_sync(0xffffffffu, v, o));
        if (tid == 0) s_maxc = v;
    }
    __syncthreads();
    float maxc = s_maxc;

    // ---- class-offset shift (BEFORE area/center, like the reference) ----
    float off = (float)mycls * (maxc + 1.0f);
    float x1 = mybox.x + off, y1 = mybox.y + off;
    float x2 = mybox.z + off, y2 = mybox.w + off;
    float area = (x2 - x1 + 1.0f) * (y2 - y1 + 1.0f);
    float cx = (x1 + x2) * 0.5f, cy = (y1 + y2) * 0.5f;
    __syncthreads();   // sm reads done; alias region reusable
    sx1[tid] = x1; sy1[tid] = y1; sx2[tid] = x2; sy2[tid] = y2;
    sar[tid] = area; scx[tid] = cx; scy[tid] = cy;
    skeep[tid] = valid ? 1 : 0;
    __syncthreads();

    // ---- fast-path NMS: first FASTN rows, 4 warps, named barrier ----
    if (tid < FASTN) {
        int keepf = skeep[tid];
        int kept = 0;
        for (int i = 0; i < FASTN; i++) {
            int ki = skeep[i];
            if (ki && keepf && tid > i) {
                float xmin = fmaxf(sx1[i], x1);
                float ymin = fmaxf(sy1[i], y1);
                float xmax = fminf(sx2[i], x2);
                float ymax = fminf(sy2[i], y2);
                float inter = fmaxf(xmax - xmin, 0.0f) * fmaxf(ymax - ymin, 0.0f);
                float denom = sar[i] + area - inter;
                if (inter > IOU_THR * denom) {      // conservative: diou <= iou
                    float iou = inter / denom;
                    float dx = scx[i] - cx, dy = scy[i] - cy;
                    float idg = dx * dx + dy * dy;
                    float ox = fmaxf(sx2[i], x2) - fminf(sx1[i], x1);
                    float oy = fmaxf(sy2[i], y2) - fminf(sy1[i], y1);
                    float odg = ox * ox + oy * oy;
                    float diou = iou - idg / fmaxf(odg, 1e-12f);
                    if (diou > IOU_THR) { keepf = 0; skeep[tid] = 0; }
                }
            }
            kept += ki;
            asm volatile("bar.sync 1, 128;" ::: "memory");
            if (kept >= MAXOUT) break;              // uniform among 128
        }
        if (tid == 0) s_fastkept = kept;
    }
    __syncthreads();

    int keepj;
    if (s_fastkept >= MAXOUT) {
        keepj = skeep[tid];          // rows >= FASTN: rank >= MAXOUT -> dropped below
    } else {
        // ---- fallback: exact full 1000-row loop (reset + rerun) ----
        skeep[tid] = valid ? 1 : 0;
        __syncthreads();
        keepj = skeep[tid];
        int kept_so_far = 0;
        for (int i = 0; i < KSEL; i++) {
            int ki = skeep[i];
            if (ki && keepj && tid > i) {
                float xmin = fmaxf(sx1[i], x1);
                float ymin = fmaxf(sy1[i], y1);
                float xmax = fminf(sx2[i], x2);
                float ymax = fminf(sy2[i], y2);
                float inter = fmaxf(xmax - xmin, 0.0f) * fmaxf(ymax - ymin, 0.0f);
                float denom = sar[i] + area - inter;
                if (inter > IOU_THR * denom) {
                    float iou = inter / denom;
                    float dx = scx[i] - cx, dy = scy[i] - cy;
                    float idg = dx * dx + dy * dy;
                    float ox = fmaxf(sx2[i], x2) - fminf(sx1[i], x1);
                    float oy = fmaxf(sy2[i], y2) - fminf(sy1[i], y1);
                    float odg = ox * ox + oy * oy;
                    float diou = iou - idg / fmaxf(odg, 1e-12f);
                    if (diou > IOU_THR) { keepj = 0; skeep[tid] = 0; }
                }
            }
            kept_so_far += ki;
            __syncthreads();
            if (kept_so_far >= MAXOUT) break;       // uniform
        }
    }

    // ---- rank via ballot scan ----
    unsigned bal = __ballot_sync(0xffffffffu, keepj != 0);
    int laneprefix = __popc(bal & ((1u << lane) - 1u));
    if (lane == 0) warptot[wid] = __popc(bal);
    __syncthreads();
    if (wid == 0) {
        unsigned v = warptot[lane];
        unsigned wi = v;
        #pragma unroll
        for (int o = 1; o < 32; o <<= 1) {
            unsigned x = __shfl_up_sync(0xffffffffu, wi, o);
            if (lane >= o) wi += x;
        }
        warptot[lane] = wi - v;
    }
    __syncthreads();
    int rank = (int)warptot[wid] + laneprefix;

    // ---- output: scores [B,100] || classes [B,100] || boxes [B,100,4], all f32 ----
    float* oS = out + (size_t)b * MAXOUT;
    float* oC = out + (size_t)B * MAXOUT + (size_t)b * MAXOUT;
    float* oB = out + (size_t)2 * B * MAXOUT + (size_t)b * MAXOUT * 4;
    if (tid < MAXOUT) {
        oS[tid] = -2.0f; oC[tid] = -2.0f;
        oB[tid * 4 + 0] = -2.0f; oB[tid * 4 + 1] = -2.0f;
        oB[tid * 4 + 2] = -2.0f; oB[tid * 4 + 3] = -2.0f;
    }
    __syncthreads();
    if (keepj && rank < MAXOUT) {
        oS[rank] = score;
        oC[rank] = (float)mycls;
        oB[rank * 4 + 0] = mybox.x; oB[rank * 4 + 1] = mybox.y;
        oB[rank * 4 + 2] = mybox.z; oB[rank * 4 + 3] = mybox.w;
    }
}

// ---------------- launch ----------------
extern "C" void kernel_launch(void* const* d_in, const int* in_sizes, int n_in,
                              void* d_out, int out_size)
{
    const float* cls[5] = {0,0,0,0,0};
    const float* reg[5] = {0,0,0,0,0};
    for (int i = 0; i < n_in; i++) {
        switch (in_sizes[i]) {
            case 16384000: cls[0] = (const float*)d_in[i]; break;
            case  4096000: cls[1] = (const float*)d_in[i]; break;
            case  1024000: cls[2] = (const float*)d_in[i]; break;
            case   266240: cls[3] = (const float*)d_in[i]; break;
            case    71680: cls[4] = (const float*)d_in[i]; break;
            case   819200: reg[0] = (const float*)d_in[i]; break;
            case   204800: reg[1] = (const float*)d_in[i]; break;
            case    51200: reg[2] = (const float*)d_in[i]; break;
            case    13312: reg[3] = (const float*)d_in[i]; break;
            case     3584: reg[4] = (const float*)d_in[i]; break;
            default: break; // anchors (unused)
        }
    }
    int total = B * NTOT;
    dim3 fg((NTOT + 255) / 256, B);
    decode_kernel<<<(total + 255) / 256, 256>>>(
        cls[0], cls[1], cls[2], cls[3], cls[4],
        reg[0], reg[1], reg[2], reg[3], reg[4]);
    thresh1_kernel<<<B, 1024>>>();
    refine_kernel<<<fg, 256>>>();
    thresh2_kernel<<<B, 1024>>>();
    compact_kernel<<<fg, 256>>>();
    select_nms_kernel<<<B, 1024>>>((float*)d_out);
}

// round 10
// speedup vs baseline: 2.0231x; 1.1346x over previous
#include <cuda_runtime.h>
#include <cuda_bf16.h>
#include <math.h>

#define B 16
#define NTOT 17064
#define KSEL 1000
#define MAXOUT 100
#define SCORE_THR 0.05f
#define IOU_THR 0.6f
#define CANDCAP 2048
#define FASTN 128

typedef unsigned long long u64;

// ---------------- scratch (static device globals; no allocations) ----------------
__device__ u64      g_key[B * NTOT];
__device__ float4   g_box[B * NTOT];
__device__ int      g_cls[B * NTOT];
__device__ unsigned g_hist[B * 1024];    // zero-init at load; re-zeroed by select
__device__ int      g_cnt[B];            // zero-init at load; re-zeroed by select
__device__ u64      g_cand[B * CANDCAP];

// ---------------- kernel 1: decode + score-linear 1024-bin histogram ----------------
__global__ __launch_bounds__(256) void decode_kernel(
    const float* __restrict__ c0, const float* __restrict__ c1,
    const float* __restrict__ c2, const float* __restrict__ c3,
    const float* __restrict__ c4,
    const float* __restrict__ r0, const float* __restrict__ r1,
    const float* __restrict__ r2, const float* __restrict__ r3,
    const float* __restrict__ r4)
{
    int t = blockIdx.x * blockDim.x + threadIdx.x;
    if (t >= B * NTOT) return;
    int b = t / NTOT;
    int a = t - b * NTOT;

    int p, hw, w, stride;
    const float *cp, *rp;
    if (a < 12800)      { p = a;         hw = 12800; w = 128; stride = 8;   cp = c0; rp = r0; }
    else if (a < 16000) { p = a - 12800; hw = 3200;  w = 64;  stride = 16;  cp = c1; rp = r1; }
    else if (a < 16800) { p = a - 16000; hw = 800;   w = 32;  stride = 32;  cp = c2; rp = r2; }
    else if (a < 17008) { p = a - 16800; hw = 208;   w = 16;  stride = 64;  cp = c3; rp = r3; }
    else                { p = a - 17008; hw = 56;    w = 8;   stride = 128; cp = c4; rp = r4; }

    // max + argmax over 80 class logits (track top-2 for sigmoid-tie semantics)
    const float* cb = cp + ((size_t)b * 80) * hw + p;
    float m1 = -INFINITY, m2 = -INFINITY;
    int i1 = 0, i2 = 0;
    #pragma unroll 8
    for (int c = 0; c < 80; c++) {
        float v = __ldg(cb + (size_t)c * hw);
        if (v > m1) { m2 = m1; i2 = i1; m1 = v; i1 = c; }
        else if (v > m2) { m2 = v; i2 = c; }
    }
    float score = 1.0f / (1.0f + expf(-m1));
    int cls = i1 + 1;
    {   // replicate jnp.argmax-over-sigmoid first-occurrence ties
        float s2 = 1.0f / (1.0f + expf(-m2));
        if (s2 == score && i2 < i1) cls = i2 + 1;
    }

    // decode box
    float px = (float)(p % w), py = (float)(p / w);
    float ccx = px * (float)stride + 0.5f * (float)stride;
    float ccy = py * (float)stride + 0.5f * (float)stride;
    const float* rb = rp + ((size_t)b * 4) * hw + p;
    float rr0 = rb[0];
    float rr1 = rb[(size_t)hw];
    float rr2 = rb[(size_t)2 * hw];
    float rr3 = rb[(size_t)3 * hw];
    float4 box;
    box.x = ccx - rr0; box.y = ccy - rr1;
    box.z = ccx + rr2; box.w = ccy + rr3;

    size_t o = (size_t)b * NTOT + a;
    g_box[o] = box;
    g_cls[o] = cls;

    // key: descending score, ties -> lower index first (matches lax.top_k)
    unsigned u = __float_as_uint(score);
    u = (u & 0x80000000u) ? ~u : (u | 0x80000000u);
    g_key[o] = ((u64)u << 32) | (u64)(0xFFFFFFFFu - (unsigned)a);

    // score-linear histogram bin (monotone in score; *1024 is exact scaling)
    int bin = (int)(score * 1024.0f);
    if (bin > 1023) bin = 1023;
    unsigned mask = __activemask();
    unsigned peers = __match_any_sync(mask, (unsigned)(b << 10) | (unsigned)bin);
    int leader = __ffs(peers) - 1;
    if ((int)(threadIdx.x & 31) == leader)
        atomicAdd(&g_hist[b * 1024 + bin], (unsigned)__popc(peers));
}

// ---------------- kernel 2: compact (full grid; per-block redundant threshold) ----------------
__global__ __launch_bounds__(256) void compact_kernel()
{
    const int b    = blockIdx.y;
    const int tid  = threadIdx.x;
    const int lane = tid & 31;
    const int wid  = tid >> 5;
    const unsigned* hist = g_hist + (size_t)b * 1024;

    __shared__ unsigned warpsum[8];
    __shared__ int s_tb;

    // thread tid owns 4 descending bins: base, base-1, base-2, base-3
    int base = 1023 - tid * 4;
    unsigned c0 = hist[base], c1 = hist[base - 1], c2 = hist[base - 2], c3 = hist[base - 3];
    unsigned sum = c0 + c1 + c2 + c3;

    // inclusive scan over threads (thread order == descending bin order)
    unsigned incl = sum;
    #pragma unroll
    for (int o = 1; o < 32; o <<= 1) {
        unsigned v = __shfl_up_sync(0xffffffffu, incl, o);
        if (lane >= o) incl += v;
    }
    if (lane == 31) warpsum[wid] = incl;
    __syncthreads();
    unsigned wbase = 0;
    #pragma unroll
    for (int ww = 0; ww < 8; ww++) wbase += (ww < wid) ? warpsum[ww] : 0u;
    unsigned cum_incl = wbase + incl;
    unsigned cum_excl = cum_incl - sum;
    if (cum_excl < (unsigned)KSEL && (unsigned)KSEL <= cum_incl) {
        unsigned running = cum_excl;
        int tb = base;
        running += c0;
        if (running < (unsigned)KSEL) { tb = base - 1; running += c1; }
        if (running < (unsigned)KSEL) { tb = base - 2; running += c2; }
        if (running < (unsigned)KSEL) { tb = base - 3; }
        s_tb = tb;
    }
    __syncthreads();
    int tb = s_tb;

    // u-space threshold: score >= tb/1024  <=>  su >= ut  (scores positive)
    float ts = (float)tb * (1.0f / 1024.0f);
    unsigned ut = __float_as_uint(ts) | 0x80000000u;

    const int a = blockIdx.x * 256 + tid;
    u64 k = 0; bool take = false;
    if (a < NTOT) {
        k = g_key[(size_t)b * NTOT + a];
        take = ((unsigned)(k >> 32) >= ut);
    }
    unsigned bal = __ballot_sync(0xffffffffu, take);
    if (bal) {
        int leader = __ffs(bal) - 1;
        int basepos = 0;
        if (lane == leader) basepos = atomicAdd(&g_cnt[b], __popc(bal));
        basepos = __shfl_sync(0xffffffffu, basepos, leader);
        if (take) {
            int pos = basepos + __popc(bal & ((1u << lane) - 1u));
            if (pos < CANDCAP) g_cand[(size_t)b * CANDCAP + pos] = k;
        }
    }
}

// ---------------- kernel 3: per-batch sort + DIoU-NMS + output (+ re-zero state) ----------------
__global__ __launch_bounds__(1024, 1) void select_nms_kernel(float* __restrict__ out)
{
    const int b    = blockIdx.x;
    const int tid  = threadIdx.x;
    const int wid  = tid >> 5;
    const int lane = tid & 31;

    __shared__ u64   sm[2048];                        // 16KB: sort buf, later x1/y1/x2/y2
    __shared__ float sar[1024], scx[1024], scy[1024]; // 12KB
    __shared__ int   skeep[1024];                     // 4KB
    __shared__ unsigned warptot[32];
    __shared__ float warpred[32];
    __shared__ float s_maxc;
    __shared__ int   s_fastkept;

    float* sx1 = (float*)&sm[0];
    float* sy1 = (float*)&sm[512];
    float* sx2 = (float*)&sm[1024];
    float* sy2 = (float*)&sm[1536];

    if (tid == 0) s_fastkept = 0;

    int C = g_cnt[b]; if (C > CANDCAP) C = CANDCAP;
    u64 v0 = (tid        < C) ? g_cand[(size_t)b * CANDCAP + tid]        : 0ULL;
    u64 v1 = (tid + 1024 < C) ? g_cand[(size_t)b * CANDCAP + tid + 1024] : 0ULL;

    // re-zero replay state (all threads have read g_cnt / cand already)
    g_hist[b * 1024 + tid] = 0u;

    // ---- hybrid bitonic sort ascending over 2048 (2 elems/thread in registers) ----
    const int i1x = tid + 1024;
    for (int kk = 2; kk <= 2048; kk <<= 1) {
        for (int j = kk >> 1; j > 0; j >>= 1) {
            if (j >= 1024) {                     // kk==2048: partner in-thread
                if (v0 > v1) { u64 t = v0; v0 = v1; v1 = t; }
            } else if (j >= 32) {                // cross-warp: smem exchange
                sm[tid] = v0; sm[i1x] = v1;
                __syncthreads();
                u64 p0 = sm[tid ^ j], p1 = sm[(tid ^ j) + 1024];
                __syncthreads();
                bool tm0 = (((tid & kk) == 0) == ((tid & j) == 0));
                bool tm1 = (((i1x & kk) == 0) == ((i1x & j) == 0));
                v0 = tm0 ? (v0 < p0 ? v0 : p0) : (v0 > p0 ? v0 : p0);
                v1 = tm1 ? (v1 < p1 ? v1 : p1) : (v1 > p1 ? v1 : p1);
            } else {                             // in-warp: shuffle exchange
                u64 p0 = __shfl_xor_sync(0xffffffffu, v0, j);
                u64 p1 = __shfl_xor_sync(0xffffffffu, v1, j);
                bool tm0 = (((tid & kk) == 0) == ((tid & j) == 0));
                bool tm1 = (((i1x & kk) == 0) == ((i1x & j) == 0));
                v0 = tm0 ? (v0 < p0 ? v0 : p0) : (v0 > p0 ? v0 : p0);
                v1 = tm1 ? (v1 < p1 ? v1 : p1) : (v1 > p1 ? v1 : p1);
            }
        }
    }
    sm[tid] = v0; sm[i1x] = v1;
    __syncthreads();
    if (tid == 0) g_cnt[b] = 0;                  // re-zero for next replay

    // ---- gather rank-tid detection ----
    bool have = (tid < KSEL);
    float score = -2.0f; int mycls = 0; float4 mybox = make_float4(0, 0, 0, 0);
    if (have) {
        u64 mk = sm[2047 - tid];                 // tid-th largest
        unsigned idx = 0xFFFFFFFFu - (unsigned)(mk & 0xFFFFFFFFull);
        unsigned su  = (unsigned)(mk >> 32);
        su = (su & 0x80000000u) ? (su & 0x7FFFFFFFu) : ~su;
        score = __uint_as_float(su);
        mycls = g_cls[(size_t)b * NTOT + idx];
        mybox = g_box[(size_t)b * NTOT + idx];
    }
    bool valid = have && (score >= SCORE_THR);

    // ---- max coordinate over valid boxes ----
    float mc = valid ? fmaxf(fmaxf(mybox.x, mybox.y), fmaxf(mybox.z, mybox.w)) : -INFINITY;
    for (int o = 16; o; o >>= 1) mc = fmaxf(mc, __shfl_xor_sync(0xffffffffu, mc, o));
    if (lane == 0) warpred[wid] = mc;
    __syncthreads();
    if (tid < 32) {
        float v = warpred[tid];
        for (int o = 16; o; o >>= 1) v = fmaxf(v, __shfl_xor_sync(0xffffffffu, v, o));
        if (tid == 0) s_maxc = v;
    }
    __syncthreads();
    float maxc = s_maxc;

    // ---- class-offset shift (BEFORE area/center, like the reference) ----
    float off = (float)mycls * (maxc + 1.0f);
    float x1 = mybox.x + off, y1 = mybox.y + off;
    float x2 = mybox.z + off, y2 = mybox.w + off;
    float area = (x2 - x1 + 1.0f) * (y2 - y1 + 1.0f);
    float cx = (x1 + x2) * 0.5f, cy = (y1 + y2) * 0.5f;
    __syncthreads();   // sm reads done; alias region reusable
    sx1[tid] = x1; sy1[tid] = y1; sx2[tid] = x2; sy2[tid] = y2;
    sar[tid] = area; scx[tid] = cx; scy[tid] = cy;
    skeep[tid] = valid ? 1 : 0;
    __syncthreads();

    // ---- fast-path NMS: first FASTN rows, 4 warps, named barrier ----
    if (tid < FASTN) {
        int keepf = skeep[tid];
        int kept = 0;
        for (int i = 0; i < FASTN; i++) {
            int ki = skeep[i];
            if (ki && keepf && tid > i) {
                float xmin = fmaxf(sx1[i], x1);
                float ymin = fmaxf(sy1[i], y1);
                float xmax = fminf(sx2[i], x2);
                float ymax = fminf(sy2[i], y2);
                float inter = fmaxf(xmax - xmin, 0.0f) * fmaxf(ymax - ymin, 0.0f);
                float denom = sar[i] + area - inter;
                if (inter > IOU_THR * denom) {      // conservative: diou <= iou
                    float iou = inter / denom;
                    float dx = scx[i] - cx, dy = scy[i] - cy;
                    float idg = dx * dx + dy * dy;
                    float ox = fmaxf(sx2[i], x2) - fminf(sx1[i], x1);
                    float oy = fmaxf(sy2[i], y2) - fminf(sy1[i], y1);
                    float odg = ox * ox + oy * oy;
                    float diou = iou - idg / fmaxf(odg, 1e-12f);
                    if (diou > IOU_THR) { keepf = 0; skeep[tid] = 0; }
                }
            }
            kept += ki;
            asm volatile("bar.sync 1, 128;" ::: "memory");
            if (kept >= MAXOUT) break;              // uniform among 128
        }
        if (tid == 0) s_fastkept = kept;
    }
    __syncthreads();

    int keepj;
    if (s_fastkept >= MAXOUT) {
        keepj = skeep[tid];          // rows >= FASTN: rank >= MAXOUT -> dropped below
    } else {
        // ---- fallback: exact full 1000-row loop (reset + rerun) ----
        skeep[tid] = valid ? 1 : 0;
        __syncthreads();
        keepj = skeep[tid];
        int kept_so_far = 0;
        for (int i = 0; i < KSEL; i++) {
            int ki = skeep[i];
            if (ki && keepj && tid > i) {
                float xmin = fmaxf(sx1[i], x1);
                float ymin = fmaxf(sy1[i], y1);
                float xmax = fminf(sx2[i], x2);
                float ymax = fminf(sy2[i], y2);
                float inter = fmaxf(xmax - xmin, 0.0f) * fmaxf(ymax - ymin, 0.0f);
                float denom = sar[i] + area - inter;
                if (inter > IOU_THR * denom) {
                    float iou = inter / denom;
                    float dx = scx[i] - cx, dy = scy[i] - cy;
                    float idg = dx * dx + dy * dy;
                    float ox = fmaxf(sx2[i], x2) - fminf(sx1[i], x1);
                    float oy = fmaxf(sy2[i], y2) - fminf(sy1[i], y1);
                    float odg = ox * ox + oy * oy;
                    float diou = iou - idg / fmaxf(odg, 1e-12f);
                    if (diou > IOU_THR) { keepj = 0; skeep[tid] = 0; }
                }
            }
            kept_so_far += ki;
            __syncthreads();
            if (kept_so_far >= MAXOUT) break;       // uniform
        }
    }

    // ---- rank via ballot scan ----
    unsigned bal = __ballot_sync(0xffffffffu, keepj != 0);
    int laneprefix = __popc(bal & ((1u << lane) - 1u));
    if (lane == 0) warptot[wid] = __popc(bal);
    __syncthreads();
    if (wid == 0) {
        unsigned v = warptot[lane];
        unsigned wi = v;
        #pragma unroll
        for (int o = 1; o < 32; o <<= 1) {
            unsigned x = __shfl_up_sync(0xffffffffu, wi, o);
            if (lane >= o) wi += x;
        }
        warptot[lane] = wi - v;
    }
    __syncthreads();
    int rank = (int)warptot[wid] + laneprefix;

    // ---- output: scores [B,100] || classes [B,100] || boxes [B,100,4], all f32 ----
    float* oS = out + (size_t)b * MAXOUT;
    float* oC = out + (size_t)B * MAXOUT + (size_t)b * MAXOUT;
    float* oB = out + (size_t)2 * B * MAXOUT + (size_t)b * MAXOUT * 4;
    if (tid < MAXOUT) {
        oS[tid] = -2.0f; oC[tid] = -2.0f;
        oB[tid * 4 + 0] = -2.0f; oB[tid * 4 + 1] = -2.0f;
        oB[tid * 4 + 2] = -2.0f; oB[tid * 4 + 3] = -2.0f;
    }
    __syncthreads();
    if (keepj && rank < MAXOUT) {
        oS[rank] = score;
        oC[rank] = (float)mycls;
        oB[rank * 4 + 0] = mybox.x; oB[rank * 4 + 1] = mybox.y;
        oB[rank * 4 + 2] = mybox.z; oB[rank * 4 + 3] = mybox.w;
    }
}

// ---------------- launch ----------------
extern "C" void kernel_launch(void* const* d_in, const int* in_sizes, int n_in,
                              void* d_out, int out_size)
{
    const float* cls[5] = {0,0,0,0,0};
    const float* reg[5] = {0,0,0,0,0};
    for (int i = 0; i < n_in; i++) {
        switch (in_sizes[i]) {
            case 16384000: cls[0] = (const float*)d_in[i]; break;
            case  4096000: cls[1] = (const float*)d_in[i]; break;
            case  1024000: cls[2] = (const float*)d_in[i]; break;
            case   266240: cls[3] = (const float*)d_in[i]; break;
            case    71680: cls[4] = (const float*)d_in[i]; break;
            case   819200: reg[0] = (const float*)d_in[i]; break;
            case   204800: reg[1] = (const float*)d_in[i]; break;
            case    51200: reg[2] = (const float*)d_in[i]; break;
            case    13312: reg[3] = (const float*)d_in[i]; break;
            case     3584: reg[4] = (const float*)d_in[i]; break;
            default: break; // anchors (unused)
        }
    }
    int total = B * NTOT;
    decode_kernel<<<(total + 255) / 256, 256>>>(
        cls[0], cls[1], cls[2], cls[3], cls[4],
        reg[0], reg[1], reg[2], reg[3], reg[4]);
    compact_kernel<<<dim3((NTOT + 255) / 256, B), 256>>>();
    select_nms_kernel<<<B, 1024>>>((float*)d_out);
}

// round 11
// speedup vs baseline: 2.1360x; 1.0558x over previous
#include <cuda_runtime.h>
#include <cuda_bf16.h>
#include <math.h>

#define B 16
#define NTOT 17064
#define NH   (NTOT/2)        /* 8532 threads per batch, 2 anchors each */
#define KSEL 1000
#define MAXOUT 100
#define SCORE_THR 0.05f
#define IOU_THR 0.6f
#define CANDCAP 2048
#define FASTN 128

typedef unsigned long long u64;

// ---------------- scratch (static device globals; no allocations) ----------------
__device__ u64      g_key[B * NTOT];
__device__ float4   g_box[B * NTOT];
__device__ int      g_cls[B * NTOT];
__device__ unsigned g_hist[B * 1024];    // zero-init at load; re-zeroed by select
__device__ int      g_cnt[B];            // zero-init at load; re-zeroed by select
__device__ u64      g_cand[B * CANDCAP];

// ---------------- kernel 1: decode (2 anchors/thread, 4 indep argmax chains) ----------------
__global__ __launch_bounds__(256) void decode_kernel(
    const float* __restrict__ c0, const float* __restrict__ c1,
    const float* __restrict__ c2, const float* __restrict__ c3,
    const float* __restrict__ c4,
    const float* __restrict__ r0, const float* __restrict__ r1,
    const float* __restrict__ r2, const float* __restrict__ r3,
    const float* __restrict__ r4)
{
    int t = blockIdx.x * blockDim.x + threadIdx.x;
    if (t >= B * NH) return;
    int b  = t / NH;
    int a2 = (t - b * NH) * 2;          // first of 2 consecutive anchors (same level/row)

    int p, hw, w, stride;
    const float *cp, *rp;
    if (a2 < 12800)      { p = a2;         hw = 12800; w = 128; stride = 8;   cp = c0; rp = r0; }
    else if (a2 < 16000) { p = a2 - 12800; hw = 3200;  w = 64;  stride = 16;  cp = c1; rp = r1; }
    else if (a2 < 16800) { p = a2 - 16000; hw = 800;   w = 32;  stride = 32;  cp = c2; rp = r2; }
    else if (a2 < 17008) { p = a2 - 16800; hw = 208;   w = 16;  stride = 64;  cp = c3; rp = r3; }
    else                 { p = a2 - 17008; hw = 56;    w = 8;   stride = 128; cp = c4; rp = r4; }

    const int h2 = hw >> 1;
    const float2* cb2 = (const float2*)(cp + (size_t)b * 80 * hw + p);
    const float2* rb2 = (const float2*)(rp + (size_t)b * 4  * hw + p);

    // 4 independent top-2 chains: [anchor e][half h] — half A = classes 0..39, half B = 40..79
    float mA1[2] = {-INFINITY, -INFINITY}, mA2[2] = {-INFINITY, -INFINITY};
    float mB1[2] = {-INFINITY, -INFINITY}, mB2[2] = {-INFINITY, -INFINITY};
    int   iA1[2] = {0, 0}, iA2[2] = {0, 0}, iB1[2] = {40, 40}, iB2[2] = {40, 40};

    #pragma unroll 4
    for (int c = 0; c < 40; c++) {
        float2 vA = __ldg(cb2 + (size_t)c * h2);
        float2 vB = __ldg(cb2 + (size_t)(c + 40) * h2);
        float va[2] = {vA.x, vA.y};
        float vb[2] = {vB.x, vB.y};
        #pragma unroll
        for (int e = 0; e < 2; e++) {
            float v = va[e];
            if (v > mA1[e])      { mA2[e] = mA1[e]; iA2[e] = iA1[e]; mA1[e] = v; iA1[e] = c; }
            else if (v > mA2[e]) { mA2[e] = v; iA2[e] = c; }
            float u = vb[e];
            if (u > mB1[e])      { mB2[e] = mB1[e]; iB2[e] = iB1[e]; mB1[e] = u; iB1[e] = c + 40; }
            else if (u > mB2[e]) { mB2[e] = u; iB2[e] = c + 40; }
        }
    }

    // box regression loads (2 anchors each)
    float2 q0 = __ldg(rb2), q1 = __ldg(rb2 + h2), q2 = __ldg(rb2 + 2 * h2), q3 = __ldg(rb2 + 3 * h2);
    float l0[2] = {q0.x, q0.y};
    float l1[2] = {q1.x, q1.y};
    float l2[2] = {q2.x, q2.y};
    float l3[2] = {q3.x, q3.y};

    int px0 = p % w, py = p / w;
    float ccy = (float)py * (float)stride + 0.5f * (float)stride;

    size_t o = (size_t)b * NTOT + a2;
    u64 kk[2];
    int cls2[2];
    #pragma unroll
    for (int e = 0; e < 2; e++) {
        // merge chains preserving first-occurrence argmax (A's indices all < B's)
        float m1, m2; int i1, i2;
        if (mB1[e] > mA1[e]) {
            m1 = mB1[e]; i1 = iB1[e];
            if (mA1[e] >= mB2[e]) { m2 = mA1[e]; i2 = iA1[e]; }
            else                  { m2 = mB2[e]; i2 = iB2[e]; }
        } else {
            m1 = mA1[e]; i1 = iA1[e];
            if (mA2[e] >= mB1[e]) { m2 = mA2[e]; i2 = iA2[e]; }
            else                  { m2 = mB1[e]; i2 = iB1[e]; }
        }

        float score = 1.0f / (1.0f + expf(-m1));
        int cls = i1 + 1;
        {   // replicate jnp.argmax-over-sigmoid first-occurrence ties
            float s2 = 1.0f / (1.0f + expf(-m2));
            if (s2 == score && i2 < i1) cls = i2 + 1;
        }
        cls2[e] = cls;

        float ccx = (float)(px0 + e) * (float)stride + 0.5f * (float)stride;
        float4 box;
        box.x = ccx - l0[e]; box.y = ccy - l1[e];
        box.z = ccx + l2[e]; box.w = ccy + l3[e];
        g_box[o + e] = box;

        unsigned u = __float_as_uint(score);
        u = (u & 0x80000000u) ? ~u : (u | 0x80000000u);
        kk[e] = ((u64)u << 32) | (u64)(0xFFFFFFFFu - (unsigned)(a2 + e));

        // score-linear histogram bin (monotone; *1024 exact power-of-two scaling)
        int bin = (int)(score * 1024.0f);
        if (bin > 1023) bin = 1023;
        unsigned mask = __activemask();
        unsigned peers = __match_any_sync(mask, (unsigned)(b << 10) | (unsigned)bin);
        int leader = __ffs(peers) - 1;
        if ((int)(threadIdx.x & 31) == leader)
            atomicAdd(&g_hist[b * 1024 + bin], (unsigned)__popc(peers));
    }

    // vectorized stores
    *(ulonglong2*)&g_key[o] = make_ulonglong2(kk[0], kk[1]);
    *(int2*)&g_cls[o] = make_int2(cls2[0], cls2[1]);
}

// ---------------- kernel 2: compact (full grid; per-block redundant threshold) ----------------
__global__ __launch_bounds__(256) void compact_kernel()
{
    const int b    = blockIdx.y;
    const int tid  = threadIdx.x;
    const int lane = tid & 31;
    const int wid  = tid >> 5;
    const unsigned* hist = g_hist + (size_t)b * 1024;

    __shared__ unsigned warpsum[8];
    __shared__ int s_tb;

    // thread tid owns 4 descending bins: base, base-1, base-2, base-3
    int base = 1023 - tid * 4;
    unsigned c0 = hist[base], c1 = hist[base - 1], c2 = hist[base - 2], c3 = hist[base - 3];
    unsigned sum = c0 + c1 + c2 + c3;

    // inclusive scan over threads (thread order == descending bin order)
    unsigned incl = sum;
    #pragma unroll
    for (int o = 1; o < 32; o <<= 1) {
        unsigned v = __shfl_up_sync(0xffffffffu, incl, o);
        if (lane >= o) incl += v;
    }
    if (lane == 31) warpsum[wid] = incl;
    __syncthreads();
    unsigned wbase = 0;
    #pragma unroll
    for (int ww = 0; ww < 8; ww++) wbase += (ww < wid) ? warpsum[ww] : 0u;
    unsigned cum_incl = wbase + incl;
    unsigned cum_excl = cum_incl - sum;
    if (cum_excl < (unsigned)KSEL && (unsigned)KSEL <= cum_incl) {
        unsigned running = cum_excl;
        int tb = base;
        running += c0;
        if (running < (unsigned)KSEL) { tb = base - 1; running += c1; }
        if (running < (unsigned)KSEL) { tb = base - 2; running += c2; }
        if (running < (unsigned)KSEL) { tb = base - 3; }
        s_tb = tb;
    }
    __syncthreads();
    int tb = s_tb;

    // u-space threshold: score >= tb/1024  <=>  su >= ut  (scores positive)
    float ts = (float)tb * (1.0f / 1024.0f);
    unsigned ut = __float_as_uint(ts) | 0x80000000u;

    const int a = blockIdx.x * 256 + tid;
    u64 k = 0; bool take = false;
    if (a < NTOT) {
        k = g_key[(size_t)b * NTOT + a];
        take = ((unsigned)(k >> 32) >= ut);
    }
    unsigned bal = __ballot_sync(0xffffffffu, take);
    if (bal) {
        int leader = __ffs(bal) - 1;
        int basepos = 0;
        if (lane == leader) basepos = atomicAdd(&g_cnt[b], __popc(bal));
        basepos = __shfl_sync(0xffffffffu, basepos, leader);
        if (take) {
            int pos = basepos + __popc(bal & ((1u << lane) - 1u));
            if (pos < CANDCAP) g_cand[(size_t)b * CANDCAP + pos] = k;
        }
    }
}

// ---------------- kernel 3: per-batch sort + DIoU-NMS + output (+ re-zero state) ----------------
__global__ __launch_bounds__(1024, 1) void select_nms_kernel(float* __restrict__ out)
{
    const int b    = blockIdx.x;
    const int tid  = threadIdx.x;
    const int wid  = tid >> 5;
    const int lane = tid & 31;

    __shared__ u64   sm[2048];                        // 16KB: sort buf, later x1/y1/x2/y2
    __shared__ float sar[1024], scx[1024], scy[1024]; // 12KB
    __shared__ int   skeep[1024];                     // 4KB
    __shared__ unsigned warptot[32];
    __shared__ float warpred[32];
    __shared__ float s_maxc;
    __shared__ int   s_fastkept;

    float* sx1 = (float*)&sm[0];
    float* sy1 = (float*)&sm[512];
    float* sx2 = (float*)&sm[1024];
    float* sy2 = (float*)&sm[1536];

    if (tid == 0) s_fastkept = 0;

    int C = g_cnt[b]; if (C > CANDCAP) C = CANDCAP;
    u64 v0 = (tid        < C) ? g_cand[(size_t)b * CANDCAP + tid]        : 0ULL;
    u64 v1 = (tid + 1024 < C) ? g_cand[(size_t)b * CANDCAP + tid + 1024] : 0ULL;

    // re-zero replay state (all threads have read g_cnt / cand already)
    g_hist[b * 1024 + tid] = 0u;

    // ---- hybrid bitonic sort ascending over 2048 (2 elems/thread in registers) ----
    const int i1x = tid + 1024;
    for (int kk = 2; kk <= 2048; kk <<= 1) {
        for (int j = kk >> 1; j > 0; j >>= 1) {
            if (j >= 1024) {                     // kk==2048: partner in-thread
                if (v0 > v1) { u64 t = v0; v0 = v1; v1 = t; }
            } else if (j >= 32) {                // cross-warp: smem exchange
                sm[tid] = v0; sm[i1x] = v1;
                __syncthreads();
                u64 p0 = sm[tid ^ j], p1 = sm[(tid ^ j) + 1024];
                __syncthreads();
                bool tm0 = (((tid & kk) == 0) == ((tid & j) == 0));
                bool tm1 = (((i1x & kk) == 0) == ((i1x & j) == 0));
                v0 = tm0 ? (v0 < p0 ? v0 : p0) : (v0 > p0 ? v0 : p0);
                v1 = tm1 ? (v1 < p1 ? v1 : p1) : (v1 > p1 ? v1 : p1);
            } else {                             // in-warp: shuffle exchange
                u64 p0 = __shfl_xor_sync(0xffffffffu, v0, j);
                u64 p1 = __shfl_xor_sync(0xffffffffu, v1, j);
                bool tm0 = (((tid & kk) == 0) == ((tid & j) == 0));
                bool tm1 = (((i1x & kk) == 0) == ((i1x & j) == 0));
                v0 = tm0 ? (v0 < p0 ? v0 : p0) : (v0 > p0 ? v0 : p0);
                v1 = tm1 ? (v1 < p1 ? v1 : p1) : (v1 > p1 ? v1 : p1);
            }
        }
    }
    sm[tid] = v0; sm[i1x] = v1;
    __syncthreads();
    if (tid == 0) g_cnt[b] = 0;                  // re-zero for next replay

    // ---- gather rank-tid detection ----
    bool have = (tid < KSEL);
    float score = -2.0f; int mycls = 0; float4 mybox = make_float4(0, 0, 0, 0);
    if (have) {
        u64 mk = sm[2047 - tid];                 // tid-th largest
        unsigned idx = 0xFFFFFFFFu - (unsigned)(mk & 0xFFFFFFFFull);
        unsigned su  = (unsigned)(mk >> 32);
        su = (su & 0x80000000u) ? (su & 0x7FFFFFFFu) : ~su;
        score = __uint_as_float(su);
        mycls = g_cls[(size_t)b * NTOT + idx];
        mybox = g_box[(size_t)b * NTOT + idx];
    }
    bool valid = have && (score >= SCORE_THR);

    // ---- max coordinate over valid boxes ----
    float mc = valid ? fmaxf(fmaxf(mybox.x, mybox.y), fmaxf(mybox.z, mybox.w)) : -INFINITY;
    for (int o = 16; o; o >>= 1) mc = fmaxf(mc, __shfl_xor_sync(0xffffffffu, mc, o));
    if (lane == 0) warpred[wid] = mc;
    __syncthreads();
    if (tid < 32) {
        float v = warpred[tid];
        for (int o = 16; o; o >>= 1) v = fmaxf(v, __shfl_xor_sync(0xffffffffu, v, o));
        if (tid == 0) s_maxc = v;
    }
    __syncthreads();
    float maxc = s_maxc;

    // ---- class-offset shift (BEFORE area/center, like the reference) ----
    float off = (float)mycls * (maxc + 1.0f);
    float x1 = mybox.x + off, y1 = mybox.y + off;
    float x2 = mybox.z + off, y2 = mybox.w + off;
    float area = (x2 - x1 + 1.0f) * (y2 - y1 + 1.0f);
    float cx = (x1 + x2) * 0.5f, cy = (y1 + y2) * 0.5f;
    __syncthreads();   // sm reads done; alias region reusable
    sx1[tid] = x1; sy1[tid] = y1; sx2[tid] = x2; sy2[tid] = y2;
    sar[tid] = area; scx[tid] = cx; scy[tid] = cy;
    skeep[tid] = valid ? 1 : 0;
    __syncthreads();

    // ---- fast-path NMS: first FASTN rows, 4 warps, named barrier ----
    if (tid < FASTN) {
        int keepf = skeep[tid];
        int kept = 0;
        for (int i = 0; i < FASTN; i++) {
            int ki = skeep[i];
            if (ki && keepf && tid > i) {
                float xmin = fmaxf(sx1[i], x1);
                float ymin = fmaxf(sy1[i], y1);
                float xmax = fminf(sx2[i], x2);
                float ymax = fminf(sy2[i], y2);
                float inter = fmaxf(xmax - xmin, 0.0f) * fmaxf(ymax - ymin, 0.0f);
                float denom = sar[i] + area - inter;
                if (inter > IOU_THR * denom) {      // conservative: diou <= iou
                    float iou = inter / denom;
                    float dx = scx[i] - cx, dy = scy[i] - cy;
                    float idg = dx * dx + dy * dy;
                    float ox = fmaxf(sx2[i], x2) - fminf(sx1[i], x1);
                    float oy = fmaxf(sy2[i], y2) - fminf(sy1[i], y1);
                    float odg = ox * ox + oy * oy;
                    float diou = iou - idg / fmaxf(odg, 1e-12f);
                    if (diou > IOU_THR) { keepf = 0; skeep[tid] = 0; }
                }
            }
            kept += ki;
            asm volatile("bar.sync 1, 128;" ::: "memory");
            if (kept >= MAXOUT) break;              // uniform among 128
        }
        if (tid == 0) s_fastkept = kept;
    }
    __syncthreads();

    int keepj;
    if (s_fastkept >= MAXOUT) {
        keepj = skeep[tid];          // rows >= FASTN: rank >= MAXOUT -> dropped below
    } else {
        // ---- fallback: exact full 1000-row loop (reset + rerun) ----
        skeep[tid] = valid ? 1 : 0;
        __syncthreads();
        keepj = skeep[tid];
        int kept_so_far = 0;
        for (int i = 0; i < KSEL; i++) {
            int ki = skeep[i];
            if (ki && keepj && tid > i) {
                float xmin = fmaxf(sx1[i], x1);
                float ymin = fmaxf(sy1[i], y1);
                float xmax = fminf(sx2[i], x2);
                float ymax = fminf(sy2[i], y2);
                float inter = fmaxf(xmax - xmin, 0.0f) * fmaxf(ymax - ymin, 0.0f);
                float denom = sar[i] + area - inter;
                if (inter > IOU_THR * denom) {
                    float iou = inter / denom;
                    float dx = scx[i] - cx, dy = scy[i] - cy;
                    float idg = dx * dx + dy * dy;
                    float ox = fmaxf(sx2[i], x2) - fminf(sx1[i], x1);
                    float oy = fmaxf(sy2[i], y2) - fminf(sy1[i], y1);
                    float odg = ox * ox + oy * oy;
                    float diou = iou - idg / fmaxf(odg, 1e-12f);
                    if (diou > IOU_THR) { keepj = 0; skeep[tid] = 0; }
                }
            }
            kept_so_far += ki;
            __syncthreads();
            if (kept_so_far >= MAXOUT) break;       // uniform
        }
    }

    // ---- rank via ballot scan ----
    unsigned bal = __ballot_sync(0xffffffffu, keepj != 0);
    int laneprefix = __popc(bal & ((1u << lane) - 1u));
    if (lane == 0) warptot[wid] = __popc(bal);
    __syncthreads();
    if (wid == 0) {
        unsigned v = warptot[lane];
        unsigned wi = v;
        #pragma unroll
        for (int o = 1; o < 32; o <<= 1) {
            unsigned x = __shfl_up_sync(0xffffffffu, wi, o);
            if (lane >= o) wi += x;
        }
        warptot[lane] = wi - v;
    }
    __syncthreads();
    int rank = (int)warptot[wid] + laneprefix;

    // ---- output: scores [B,100] || classes [B,100] || boxes [B,100,4], all f32 ----
    float* oS = out + (size_t)b * MAXOUT;
    float* oC = out + (size_t)B * MAXOUT + (size_t)b * MAXOUT;
    float* oB = out + (size_t)2 * B * MAXOUT + (size_t)b * MAXOUT * 4;
    if (tid < MAXOUT) {
        oS[tid] = -2.0f; oC[tid] = -2.0f;
        oB[tid * 4 + 0] = -2.0f; oB[tid * 4 + 1] = -2.0f;
        oB[tid * 4 + 2] = -2.0f; oB[tid * 4 + 3] = -2.0f;
    }
    __syncthreads();
    if (keepj && rank < MAXOUT) {
        oS[rank] = score;
        oC[rank] = (float)mycls;
        oB[rank * 4 + 0] = mybox.x; oB[rank * 4 + 1] = mybox.y;
        oB[rank * 4 + 2] = mybox.z; oB[rank * 4 + 3] = mybox.w;
    }
}

// ---------------- launch ----------------
extern "C" void kernel_launch(void* const* d_in, const int* in_sizes, int n_in,
                              void* d_out, int out_size)
{
    const float* cls[5] = {0,0,0,0,0};
    const float* reg[5] = {0,0,0,0,0};
    for (int i = 0; i < n_in; i++) {
        switch (in_sizes[i]) {
            case 16384000: cls[0] = (const float*)d_in[i]; break;
            case  4096000: cls[1] = (const float*)d_in[i]; break;
            case  1024000: cls[2] = (const float*)d_in[i]; break;
            case   266240: cls[3] = (const float*)d_in[i]; break;
            case    71680: cls[4] = (const float*)d_in[i]; break;
            case   819200: reg[0] = (const float*)d_in[i]; break;
            case   204800: reg[1] = (const float*)d_in[i]; break;
            case    51200: reg[2] = (const float*)d_in[i]; break;
            case    13312: reg[3] = (const float*)d_in[i]; break;
            case     3584: reg[4] = (const float*)d_in[i]; break;
            default: break; // anchors (unused)
        }
    }
    int totalh = B * NH;
    decode_kernel<<<(totalh + 255) / 256, 256>>>(
        cls[0], cls[1], cls[2], cls[3], cls[4],
        reg[0], reg[1], reg[2], reg[3], reg[4]);
    compact_kernel<<<dim3((NTOT + 255) / 256, B), 256>>>();
    select_nms_kernel<<<B, 1024>>>((float*)d_out);
}